// round 14
// baseline (speedup 1.0000x reference)
#include <cuda_runtime.h>
#include <math_constants.h>
#include <cuda_fp16.h>
#include <cstdint>

// ---------------------------------------------------------------------------
// Net_40312563041045: 4-layer max-tempered MLP
//   h = 0.8 * (X @ W^T) + 0.2 * max_k(W[o,k] * x[b,k]) + b
// B=1024, 256 -> 512 -> 512 -> 512 -> 1, fp32.
//
// R14 == R13 resubmitted (previous round was an infra failure, not a kernel
// result). R12 minus redundant work:
//  - fp16 tiles come pre-converted from global (prep kernel for W + x;
//    layer epilogue emits act16): max warps lose the per-chunk convert pass.
//  - W pre-split into tf32 hi/lo by prep: gemm warps lose W splits.
//  - X lo-part passed as raw (f - hi): mma.tf32 truncates, second cvt dropped.
// 64x32 tile, 256 threads (4 max warps fp16 HMUL2/HMAX2 + 4 gemm warps
// mma.sync tf32 3-pass), grid 256, 2 blocks/SM (dynamic smem 52.2KB).
// ---------------------------------------------------------------------------

#define BETA 0.2f

// buffer layout (float offsets)
#define XF_F   0
#define WHI_F  2304
#define WLO_F  3456
#define X16_F  4608     // 64 rows * 40 halves = 1280 float-units
#define W16_F  5888     // 32 rows * 40 halves = 640 float-units
#define BUF_F  6528
#define SMEM_BYTES (2 * BUF_F * 4)   // 52224

// ---------------- global scratch ------------------------------------------
__device__ float  g_actA[1024 * 512], g_actB[1024 * 512];
__device__ __half g_a16A[1024 * 512], g_a16B[1024 * 512];
__device__ __half g_x16[1024 * 256];
__device__ __half g_W116[512 * 256], g_W216[512 * 512], g_W316[512 * 512];
__device__ float  g_W1hi[512 * 256], g_W1lo[512 * 256];
__device__ float  g_W2hi[512 * 512], g_W2lo[512 * 512];
__device__ float  g_W3hi[512 * 512], g_W3lo[512 * 512];

// ---------------- helpers --------------------------------------------------
__device__ __forceinline__ unsigned smem_u32(const void* p) {
    return (unsigned)__cvta_generic_to_shared(p);
}
__device__ __forceinline__ void cp16(unsigned dst, const void* src) {
    asm volatile("cp.async.ca.shared.global [%0], [%1], 16;\n" :: "r"(dst), "l"(src));
}
__device__ __forceinline__ float tf32_of(float v) {
    uint32_t t;
    asm("cvt.rna.tf32.f32 %0, %1;" : "=r"(t) : "f"(v));
    return __uint_as_float(t);
}
__device__ __forceinline__ void mma_tf32(float c[4], const uint32_t a[4],
                                         const uint32_t b[2]) {
    asm volatile(
        "mma.sync.aligned.m16n8k8.row.col.f32.tf32.tf32.f32 "
        "{%0,%1,%2,%3}, {%4,%5,%6,%7}, {%8,%9}, {%0,%1,%2,%3};"
        : "+f"(c[0]), "+f"(c[1]), "+f"(c[2]), "+f"(c[3])
        : "r"(a[0]), "r"(a[1]), "r"(a[2]), "r"(a[3]), "r"(b[0]), "r"(b[1]));
}

// ---------------- prep: W -> {tf32 hi, tf32 lo, fp16}; x -> fp16 -----------
// float4 ranges: x [0,65536) W1 [65536,98304) W2 [98304,163840) W3 [163840,229376)
__global__ void __launch_bounds__(256)
prep_kernel(const float* __restrict__ x, const float* __restrict__ W1,
            const float* __restrict__ W2, const float* __restrict__ W3)
{
    const int i = blockIdx.x * 256 + threadIdx.x;
    if (i < 65536) {
        float4 v = ((const float4*)x)[i];
        __half2 h0 = __floats2half2_rn(v.x, v.y);
        __half2 h1 = __floats2half2_rn(v.z, v.w);
        ((__half2*)g_x16)[i * 2]     = h0;
        ((__half2*)g_x16)[i * 2 + 1] = h1;
        return;
    }
    const float* src; float* hi; float* lo; __half* h16; int off;
    if (i < 98304)       { src = W1; hi = g_W1hi; lo = g_W1lo; h16 = g_W116; off = i - 65536; }
    else if (i < 163840) { src = W2; hi = g_W2hi; lo = g_W2lo; h16 = g_W216; off = i - 98304; }
    else                 { src = W3; hi = g_W3hi; lo = g_W3lo; h16 = g_W316; off = i - 163840; }
    float4 v = ((const float4*)src)[off];
    float4 h, l;
    h.x = tf32_of(v.x); l.x = v.x - h.x;
    h.y = tf32_of(v.y); l.y = v.y - h.y;
    h.z = tf32_of(v.z); l.z = v.z - h.z;
    h.w = tf32_of(v.w); l.w = v.w - h.w;
    ((float4*)hi)[off] = h;
    ((float4*)lo)[off] = l;
    ((__half2*)h16)[off * 2]     = __floats2half2_rn(v.x, v.y);
    ((__half2*)h16)[off * 2 + 1] = __floats2half2_rn(v.z, v.w);
}

// ---------------- fused warp-specialized layer ------------------------------
// Grid 256 = 16 (m: 64 rows) x 16 (n: 32 cols), 256 threads:
//   warps 0-3: MAX term, packed fp16 over staged fp16 tiles
//   warps 4-7: LINEAR term, mma.sync tf32 3-pass (X split in-register)
template <int K>
__global__ void __launch_bounds__(256, 2)
layer_fused(const float* __restrict__ Xf, const __half* __restrict__ X16g,
            const float* __restrict__ Whi, const float* __restrict__ Wlo,
            const __half* __restrict__ W16g, const float* __restrict__ bias,
            float* __restrict__ act, __half* __restrict__ act16, int O)
{
    extern __shared__ float smf[];
    const unsigned sb = smem_u32(smf);
    const int tid = threadIdx.x;
    const int wid = tid >> 5;
    const int lane = tid & 31;
    const int m0 = (blockIdx.x & 15) * 64;
    const int n0 = (blockIdx.x >> 4) * 32;

    // staging maps
    const int xrow = tid >> 2;          // 0..63 (XF: 2 chunks, X16: 1 chunk)
    const int xq   = (tid & 3) * 4;     // XF float col
    const int xhc  = (tid & 3) * 8;     // X16 half col
    const int wrow = tid >> 3;          // 0..31 (WHI/WLO: 1 chunk each)
    const int wq   = (tid & 7) * 4;
    const int w16r = (tid & 127) >> 2;  // 0..31 (W16: threads 0-127)
    const int w16c = (tid & 3) * 8;

    const float*  xg  = Xf   + (size_t)(m0 + xrow) * K + xq;
    const __half* x6g = X16g + (size_t)(m0 + xrow) * K + xhc;
    const float*  whg = Whi  + (size_t)(n0 + wrow) * K + wq;
    const float*  wlg = Wlo  + (size_t)(n0 + wrow) * K + wq;
    const __half* w6g = W16g + (size_t)(n0 + w16r) * K + w16c;

    // max-role mapping (threads 0-127)
    const int tcol = tid & 7;
    const int trow = tid >> 3;
    // gemm-role mapping (verified fragment indices)
    const int gw = wid - 4;
    const int wm = gw & 1;
    const int wn = gw >> 1;
    const int lr = lane >> 2;
    const int lw = lane & 3;

    __half2 mx[4][4];
    const __half2 ninf = __halves2half2(__ushort_as_half(0xFC00),
                                        __ushort_as_half(0xFC00));
#pragma unroll
    for (int i = 0; i < 4; i++)
#pragma unroll
        for (int j = 0; j < 4; j++) mx[i][j] = ninf;
    float acc[2][2][4];
#pragma unroll
    for (int mt = 0; mt < 2; mt++)
#pragma unroll
        for (int nt = 0; nt < 2; nt++)
#pragma unroll
            for (int e = 0; e < 4; e++) acc[mt][nt][e] = 0.0f;

    const int NCH = K / 32;

    // stage chunk (k offset k0) into buffer at float-offset bbF
    auto stage = [&](int k0, unsigned bbF) {
        const unsigned bbB = bbF * 4u;
        cp16(sb + bbB + (unsigned)(xrow * 36 + xq) * 4,       xg + k0);
        cp16(sb + bbB + (unsigned)(xrow * 36 + xq) * 4 + 64,  xg + k0 + 16);
        cp16(sb + bbB + (WHI_F + wrow * 36 + wq) * 4u,        whg + k0);
        cp16(sb + bbB + (WLO_F + wrow * 36 + wq) * 4u,        wlg + k0);
        cp16(sb + bbB + X16_F * 4u + (unsigned)(xrow * 40 + xhc) * 2, x6g + k0);
        if (tid < 128)
            cp16(sb + bbB + W16_F * 4u + (unsigned)(w16r * 40 + w16c) * 2, w6g + k0);
        asm volatile("cp.async.commit_group;\n");
    };

    stage(0, 0);

    for (int c = 0; c < NCH; ++c) {
        const int buf = c & 1;
        if (c + 1 < NCH) {
            stage((c + 1) * 32, (unsigned)((buf ^ 1) * BUF_F));
            asm volatile("cp.async.wait_group 1;\n");
        } else {
            asm volatile("cp.async.wait_group 0;\n");
        }
        __syncthreads();

        const float* B = smf + buf * BUF_F;

        if (wid < 4) {
            // -------- MAX warps: packed fp16 over staged tiles -------------
            const __half* X16 = (const __half*)(B + X16_F);
            const __half* W16 = (const __half*)(B + W16_F);
#pragma unroll
            for (int kk = 0; kk < 32; kk += 8) {
                uint4 xv[4], wv[4];
#pragma unroll
                for (int i = 0; i < 4; i++)
                    xv[i] = *(const uint4*)&X16[(trow * 4 + i) * 40 + kk];
#pragma unroll
                for (int j = 0; j < 4; j++)
                    wv[j] = *(const uint4*)&W16[(tcol + 8 * j) * 40 + kk];
#pragma unroll
                for (int i = 0; i < 4; i++)
#pragma unroll
                    for (int j = 0; j < 4; j++) {
                        const __half2* xh = (const __half2*)&xv[i];
                        const __half2* wh = (const __half2*)&wv[j];
#pragma unroll
                        for (int e = 0; e < 4; e++)
                            mx[i][j] = __hmax2(mx[i][j], __hmul2(xh[e], wh[e]));
                    }
            }
        } else {
            // -------- GEMM warps: X split in-register, W pre-split ---------
            const float* XF = B + XF_F;
            const uint32_t* WH = (const uint32_t*)(B + WHI_F);
            const uint32_t* WL = (const uint32_t*)(B + WLO_F);
#pragma unroll
            for (int kc = 0; kc < 32; kc += 8) {
                uint32_t ah[2][4], al[2][4];
#pragma unroll
                for (int mt = 0; mt < 2; mt++) {
                    const int base = (wm * 32 + mt * 16 + lr) * 36 + kc + lw;
                    float f0 = XF[base],     f1 = XF[base + 8 * 36];
                    float f2 = XF[base + 4], f3 = XF[base + 8 * 36 + 4];
                    float h0 = tf32_of(f0), h1 = tf32_of(f1);
                    float h2 = tf32_of(f2), h3 = tf32_of(f3);
                    ah[mt][0] = __float_as_uint(h0); al[mt][0] = __float_as_uint(f0 - h0);
                    ah[mt][1] = __float_as_uint(h1); al[mt][1] = __float_as_uint(f1 - h1);
                    ah[mt][2] = __float_as_uint(h2); al[mt][2] = __float_as_uint(f2 - h2);
                    ah[mt][3] = __float_as_uint(h3); al[mt][3] = __float_as_uint(f3 - h3);
                }
#pragma unroll
                for (int nt = 0; nt < 2; nt++) {
                    const int base = (wn * 16 + nt * 8 + lr) * 36 + kc + lw;
                    uint32_t bh[2] = { WH[base], WH[base + 4] };
                    uint32_t bl[2] = { WL[base], WL[base + 4] };
#pragma unroll
                    for (int mt = 0; mt < 2; mt++) {
                        mma_tf32(acc[mt][nt], ah[mt], bh);
                        mma_tf32(acc[mt][nt], ah[mt], bl);
                        mma_tf32(acc[mt][nt], al[mt], bh);
                    }
                }
            }
        }
        __syncthreads();
    }

    // ---- epilogue ----
    float* mxs = smf;   // [64][36]; buffer 0 free (last chunk uses buf 1)
    if (wid < 4) {
#pragma unroll
        for (int i = 0; i < 4; i++)
#pragma unroll
            for (int j = 0; j < 4; j++) {
                float m = fmaxf(__low2float(mx[i][j]), __high2float(mx[i][j]));
                mxs[(trow * 4 + i) * 36 + tcol + 8 * j] = BETA * m;
            }
    }
    __syncthreads();

    if (wid >= 4) {
#pragma unroll
        for (int mt = 0; mt < 2; mt++) {
            const int r0 = wm * 32 + mt * 16 + lr;
#pragma unroll
            for (int nt = 0; nt < 2; nt++) {
                const int cc = wn * 16 + nt * 8 + lw * 2;
                const float2 bia = *(const float2*)&bias[n0 + cc];

                float a0 = 0.8f * acc[mt][nt][0] + bia.x + mxs[r0 * 36 + cc];
                float a1 = 0.8f * acc[mt][nt][1] + bia.y + mxs[r0 * 36 + cc + 1];
                float a2 = 0.8f * acc[mt][nt][2] + bia.x + mxs[(r0 + 8) * 36 + cc];
                float a3 = 0.8f * acc[mt][nt][3] + bia.y + mxs[(r0 + 8) * 36 + cc + 1];

                const size_t o0 = (size_t)(m0 + r0) * O + n0 + cc;
                const size_t o1 = (size_t)(m0 + r0 + 8) * O + n0 + cc;
                *(float2*)&act[o0] = make_float2(a0, a1);
                *(float2*)&act[o1] = make_float2(a2, a3);
                *(__half2*)&act16[o0] = __floats2half2_rn(a0, a1);
                *(__half2*)&act16[o1] = __floats2half2_rn(a2, a3);
            }
        }
    }
}

// ---------------- final layer ----------------------------------------------
__global__ void __launch_bounds__(256)
layer4_kernel(const float* __restrict__ X, const float* __restrict__ W,
              const float* __restrict__ bias, float* __restrict__ out, int B)
{
    const int row = blockIdx.x * 8 + (threadIdx.x >> 5);
    const int lane = threadIdx.x & 31;
    if (row >= B) return;

    const float4* xr = (const float4*)(X + (size_t)row * 512);
    const float4* wr = (const float4*)W;

    float acc = 0.0f;
    float mx = -CUDART_INF_F;
#pragma unroll
    for (int it = 0; it < 4; ++it) {
        float4 x = xr[lane + 32 * it];
        float4 w = wr[lane + 32 * it];
        float p0 = x.x * w.x, p1 = x.y * w.y, p2 = x.z * w.z, p3 = x.w * w.w;
        acc += (p0 + p1) + (p2 + p3);
        mx = fmaxf(fmaxf(mx, fmaxf(p0, p1)), fmaxf(p2, p3));
    }
#pragma unroll
    for (int o = 16; o > 0; o >>= 1) {
        acc += __shfl_xor_sync(0xffffffff, acc, o);
        mx = fmaxf(mx, __shfl_xor_sync(0xffffffff, mx, o));
    }
    if (lane == 0)
        out[row] = (1.0f - BETA) * acc + BETA * mx + bias[0];
}

// ---------------- launch ----------------------------------------------------
extern "C" void kernel_launch(void* const* d_in, const int* in_sizes, int n_in,
                              void* d_out, int out_size)
{
    const float* x  = (const float*)d_in[0];
    const float* W1 = (const float*)d_in[1];
    const float* b1 = (const float*)d_in[2];
    const float* W2 = (const float*)d_in[3];
    const float* b2 = (const float*)d_in[4];
    const float* W3 = (const float*)d_in[5];
    const float* b3 = (const float*)d_in[6];
    const float* W4 = (const float*)d_in[7];
    const float* b4 = (const float*)d_in[8];
    float* out = (float*)d_out;

    const int WID = in_sizes[2];        // 512
    const int IN  = in_sizes[1] / WID;  // 256
    const int B   = in_sizes[0] / IN;   // 1024

    float *actA, *actB, *w1h, *w1l, *w2h, *w2l, *w3h, *w3l;
    __half *a16A, *a16B, *x16, *w116, *w216, *w316;
    cudaGetSymbolAddress((void**)&actA, g_actA);
    cudaGetSymbolAddress((void**)&actB, g_actB);
    cudaGetSymbolAddress((void**)&a16A, g_a16A);
    cudaGetSymbolAddress((void**)&a16B, g_a16B);
    cudaGetSymbolAddress((void**)&x16, g_x16);
    cudaGetSymbolAddress((void**)&w116, g_W116);
    cudaGetSymbolAddress((void**)&w216, g_W216);
    cudaGetSymbolAddress((void**)&w316, g_W316);
    cudaGetSymbolAddress((void**)&w1h, g_W1hi);
    cudaGetSymbolAddress((void**)&w1l, g_W1lo);
    cudaGetSymbolAddress((void**)&w2h, g_W2hi);
    cudaGetSymbolAddress((void**)&w2l, g_W2lo);
    cudaGetSymbolAddress((void**)&w3h, g_W3hi);
    cudaGetSymbolAddress((void**)&w3l, g_W3lo);

    cudaFuncSetAttribute(layer_fused<256>,
                         cudaFuncAttributeMaxDynamicSharedMemorySize, SMEM_BYTES);
    cudaFuncSetAttribute(layer_fused<512>,
                         cudaFuncAttributeMaxDynamicSharedMemorySize, SMEM_BYTES);

    prep_kernel<<<896, 256>>>(x, W1, W2, W3);

    const dim3 blk(256);
    const dim3 grid(256);   // 16 m-tiles x 16 n-tiles of 64x32

    layer_fused<256><<<grid, blk, SMEM_BYTES>>>(x, x16, w1h, w1l, w116, b1,
                                                actA, a16A, WID);
    layer_fused<512><<<grid, blk, SMEM_BYTES>>>(actA, a16A, w2h, w2l, w216, b2,
                                                actB, a16B, WID);
    layer_fused<512><<<grid, blk, SMEM_BYTES>>>(actB, a16B, w3h, w3l, w316, b3,
                                                actA, a16A, WID);
    layer4_kernel<<<B / 8, blk>>>(actA, W4, b4, out, B);
}